// round 1
// baseline (speedup 1.0000x reference)
#include <cuda_runtime.h>
#include <math.h>

// ---------------- static scratch (allocation-free rule) ----------------
__device__ float g_h   [2000*512];
__device__ float g_xA1 [4000*256];
__device__ float g_xB1 [4000*256];
__device__ float g_xA2 [4000*256];
__device__ float g_xB2 [4000*256];
__device__ float g_ax  [4000*256];
__device__ float g_ux  [4000*256];
__device__ float g_s0  [2u*2000*2000];
__device__ float g_T1  [2000*256];
__device__ float g_Ssym[256*256];
__device__ float g_cs  [2*4096];
__device__ float g_u   [2*2048];
__device__ float g_v   [2*2048];
__device__ float g_Rf  [2*2048];
__device__ float g_Cf  [2*2048];
__device__ float g_sq  [4*2048];
__device__ float g_gmax[2];

// ---------------- reductions ----------------
__device__ __forceinline__ float warpReduceSum(float v){
#pragma unroll
    for (int o=16;o;o>>=1) v += __shfl_xor_sync(0xffffffffu, v, o);
    return v;
}
__device__ __forceinline__ float warpReduceMax(float v){
#pragma unroll
    for (int o=16;o;o>>=1) v = fmaxf(v, __shfl_xor_sync(0xffffffffu, v, o));
    return v;
}
__device__ __forceinline__ float blockReduceSum256(float v){
    __shared__ float sm[8];
    float w = warpReduceSum(v);
    int wi = threadIdx.x>>5, ln = threadIdx.x&31;
    if (ln==0) sm[wi] = w;
    __syncthreads();
    if (wi==0){ float t = (ln<8)?sm[ln]:0.f; t = warpReduceSum(t); if (ln==0) sm[0]=t; }
    __syncthreads();
    float r = sm[0];
    __syncthreads();
    return r;
}
__device__ __forceinline__ float blockReduceMax256(float v){
    __shared__ float sm[8];
    float w = warpReduceMax(v);
    int wi = threadIdx.x>>5, ln = threadIdx.x&31;
    if (ln==0) sm[wi] = w;
    __syncthreads();
    if (wi==0){ float t = (ln<8)?sm[ln]:-1e30f; t = warpReduceMax(t); if (ln==0) sm[0]=t; }
    __syncthreads();
    float r = sm[0];
    __syncthreads();
    return r;
}

// ---------------- generic fp32 GEMM ----------------
// C[M,N] = op: act( (TA? A^T:A) @ (kscale .* (TB? B^T:B)) + bias + addend (+ C if accum) ) .* mscale
// TA: A is [K,M] (A[k*lda+m]) else [M,K]; TB: B is [N,K] (B[n*ldb+k]) else [K,N].
// act: 0 none, 1 relu, 2 sigmoid, 3 dist (uses xsq/ysq/gmax, ignores bias).
#define BM 128
#define BN 64
#define BK 16

template<bool TA, bool TB>
__global__ __launch_bounds__(256) void gemm_k(
    int M, int N, int K,
    const float* __restrict__ A, int lda,
    const float* __restrict__ B, int ldb,
    float* __restrict__ C, int ldc,
    const float* __restrict__ bias,
    const float* __restrict__ kscale,
    const float* __restrict__ mscale,
    const float* __restrict__ addend, int ldadd,
    int act, int accum,
    const float* __restrict__ xsq, const float* __restrict__ ysq,
    float* __restrict__ gmax)
{
    __shared__ float As[BK][BM+4];
    __shared__ float Bs[BK][BN+4];
    int tid = threadIdx.x;
    int m0 = blockIdx.y * BM;
    int n0 = blockIdx.x * BN;
    int tx = tid & 15, ty = tid >> 4;
    int ml = ty*8, nl = tx*4;

    float acc[8][4];
#pragma unroll
    for (int i=0;i<8;++i)
#pragma unroll
        for (int j=0;j<4;++j) acc[i][j] = 0.f;

    for (int k0 = 0; k0 < K; k0 += BK){
        // ---- load A tile ----
        if (!TA){
#pragma unroll
            for (int it=0; it<2; ++it){
                int idx = it*256 + tid;
                int row = idx >> 2;
                int kc  = (idx & 3) << 2;
                float4 vv = make_float4(0.f,0.f,0.f,0.f);
                int gm = m0 + row;
                if (gm < M) vv = *(const float4*)(A + (size_t)gm*lda + k0 + kc);
                As[kc+0][row]=vv.x; As[kc+1][row]=vv.y; As[kc+2][row]=vv.z; As[kc+3][row]=vv.w;
            }
        } else {
#pragma unroll
            for (int it=0; it<2; ++it){
                int idx = it*256 + tid;
                int kk = idx >> 5;
                int mc = (idx & 31) << 2;
                float4 vv = make_float4(0.f,0.f,0.f,0.f);
                int gm = m0 + mc;
                if (gm < M) vv = *(const float4*)(A + (size_t)(k0+kk)*lda + gm);
                *(float4*)(&As[kk][mc]) = vv;
            }
        }
        // ---- load B tile ----
        if (!TB){
            int kk = tid >> 4;
            int nc = (tid & 15) << 2;
            float4 vv = make_float4(0.f,0.f,0.f,0.f);
            int gn = n0 + nc;
            if (gn < N) vv = *(const float4*)(B + (size_t)(k0+kk)*ldb + gn);
            if (kscale){ float s = kscale[k0+kk]; vv.x*=s; vv.y*=s; vv.z*=s; vv.w*=s; }
            *(float4*)(&Bs[kk][nc]) = vv;
        } else {
            int nr = tid >> 2;
            int kc = (tid & 3) << 2;
            float4 vv = make_float4(0.f,0.f,0.f,0.f);
            int gn = n0 + nr;
            if (gn < N) vv = *(const float4*)(B + (size_t)gn*ldb + k0 + kc);
            if (kscale){
                vv.x *= kscale[k0+kc+0]; vv.y *= kscale[k0+kc+1];
                vv.z *= kscale[k0+kc+2]; vv.w *= kscale[k0+kc+3];
            }
            Bs[kc+0][nr]=vv.x; Bs[kc+1][nr]=vv.y; Bs[kc+2][nr]=vv.z; Bs[kc+3][nr]=vv.w;
        }
        __syncthreads();
        // ---- compute ----
#pragma unroll
        for (int kk=0; kk<BK; ++kk){
            float4 a0 = *(const float4*)(&As[kk][ml]);
            float4 a1 = *(const float4*)(&As[kk][ml+4]);
            float4 b0 = *(const float4*)(&Bs[kk][nl]);
            float av[8] = {a0.x,a0.y,a0.z,a0.w,a1.x,a1.y,a1.z,a1.w};
            float bv[4] = {b0.x,b0.y,b0.z,b0.w};
#pragma unroll
            for (int i=0;i<8;++i)
#pragma unroll
                for (int j=0;j<4;++j) acc[i][j] = fmaf(av[i], bv[j], acc[i][j]);
        }
        __syncthreads();
    }
    // ---- epilogue ----
    float dmax = 0.f;
#pragma unroll
    for (int i=0;i<8;++i){
        int gm = m0 + ml + i;
        if (gm < M){
#pragma unroll
            for (int j=0;j<4;++j){
                int gn = n0 + nl + j;
                if (gn < N){
                    float v = acc[i][j];
                    size_t cidx = (size_t)gm*ldc + gn;
                    if (accum)  v += C[cidx];
                    if (addend) v += addend[(size_t)gm*ldadd + gn];
                    if (bias)   v += bias[gn];
                    if (act==1)      v = fmaxf(v, 0.f);
                    else if (act==2) v = 1.f/(1.f+expf(-v));
                    else if (act==3){
                        v = sqrtf(fmaxf(xsq[gm]+ysq[gn]-2.f*v, 0.f));
                        dmax = fmaxf(dmax, v);
                    }
                    if (mscale) v *= mscale[gm];
                    C[cidx] = v;
                }
            }
        }
    }
    if (act==3){
        __shared__ float red[256];
        red[tid] = dmax; __syncthreads();
        for (int s=128;s;s>>=1){ if (tid<s) red[tid]=fmaxf(red[tid],red[tid+s]); __syncthreads(); }
        if (tid==0) atomicMax((int*)gmax, __float_as_int(red[0]));
    }
}

// ---------------- elementwise / reduction kernels ----------------
__global__ void zero_k(float* p, int n){
    int i = blockIdx.x*blockDim.x + threadIdx.x;
    if (i < n) p[i] = 0.f;
}
__global__ void recip_clamp_k(float* p, int n){
    int i = blockIdx.x*blockDim.x + threadIdx.x;
    if (i < n) p[i] = 1.f / fmaxf(p[i], 1e-12f);
}
// row L2 normalize, 256 cols, one block per row
__global__ void l2norm_k(float* __restrict__ x){
    int row = blockIdx.x;
    float v = x[(size_t)row*256 + threadIdx.x];
    float s = blockReduceSum256(v*v);
    float nrm = sqrtf(s);
    x[(size_t)row*256 + threadIdx.x] = v / fmaxf(nrm, 1e-12f);
}
// row sum of squares, 256 cols
__global__ void rowsq_k(const float* __restrict__ x, float* __restrict__ out){
    int row = blockIdx.x;
    float v = x[(size_t)row*256 + threadIdx.x];
    float s = blockReduceSum256(v*v);
    if (threadIdx.x==0) out[row] = s;
}
// Kp = 1 - d/max
__global__ void simfin_k(float* __restrict__ p, const float* __restrict__ gmax, int n){
    int i = blockIdx.x*blockDim.x + threadIdx.x;
    if (i < n){
        float inv = 1.f / gmax[0];
        p[i] = 1.f - p[i]*inv;
    }
}
// column abs-sum of A[4000,4000]; grid (16,32), block 256
__global__ void colabs_k(const float* __restrict__ A, float* __restrict__ acc){
    int j  = blockIdx.x*256 + threadIdx.x;
    int r0 = blockIdx.y*125;
    if (j >= 4000) return;
    float s = 0.f;
    for (int i=0;i<125;++i) s += fabsf(A[(size_t)(r0+i)*4000 + j]);
    atomicAdd(&acc[j], s);
}
// Ssym = (A + A^T)/2 for 256x256
__global__ void ssym_k(const float* __restrict__ A, float* __restrict__ S){
    int i = blockIdx.x, j = threadIdx.x;
    S[i*256+j] = 0.5f*(A[i*256+j] + A[j*256+i]);
}
// softmax(alpha*aff) + eps, in place on 2000-wide rows; off-block adds 2000*exp(-Mx) to denom.
// grid (2000 rows, 2 z)
__global__ void softmax_k(float* __restrict__ s0base){
    int z = blockIdx.y, row = blockIdx.x, tid = threadIdx.x;
    float* p = s0base + (size_t)z*4000000 + (size_t)row*2000;
    float a[8]; float mx = -1e30f;
#pragma unroll
    for (int i=0;i<8;++i){
        int c = tid + i*256;
        if (c < 2000){ a[i] = 200.f*p[c]; mx = fmaxf(mx, a[i]); }
        else a[i] = -1e30f;
    }
    float rowmax = blockReduceMax256(mx);
    float Mx = fmaxf(rowmax, 0.f);
    float lsum = 0.f;
#pragma unroll
    for (int i=0;i<8;++i){
        int c = tid + i*256;
        if (c < 2000){ a[i] = expf(a[i]-Mx); lsum += a[i]; }
    }
    float tot = blockReduceSum256(lsum) + 2000.f*expf(-Mx);
    float inv = 1.f/tot;
#pragma unroll
    for (int i=0;i<8;++i){
        int c = tid + i*256;
        if (c < 2000) p[c] = a[i]*inv + 1e-4f;
    }
}
// sinkhorn col pass: u[j] += sum_i s0[i,j]*R[i],  R = first?1:1/vraw. grid (8,16,2)
__global__ void sink_col_k(const float* __restrict__ s0base, const float* __restrict__ vraw,
                           float* __restrict__ uraw, int first){
    int z = blockIdx.z;
    const float* s0 = s0base + (size_t)z*4000000;
    __shared__ float Rs[125];
    int r0 = blockIdx.y*125;
    if (threadIdx.x < 125)
        Rs[threadIdx.x] = first ? 1.f : 1.f/vraw[z*2048 + r0 + threadIdx.x];
    __syncthreads();
    int j = blockIdx.x*256 + threadIdx.x;
    if (j < 2000){
        float s = 0.f;
        for (int i=0;i<125;++i) s += s0[(size_t)(r0+i)*2000 + j]*Rs[i];
        atomicAdd(&uraw[z*2048 + j], s);
    }
}
// sinkhorn row pass: v[i] = sum_j s0[i,j]*(1/uraw[j]). grid (250,2), 8 warps = 8 rows/block
__global__ void sink_row_k(const float* __restrict__ s0base, const float* __restrict__ uraw,
                           float* __restrict__ vraw){
    int z = blockIdx.y;
    const float* s0 = s0base + (size_t)z*4000000;
    __shared__ float Cs[2000];
    for (int i=threadIdx.x; i<2000; i+=256) Cs[i] = 1.f/uraw[z*2048 + i];
    __syncthreads();
    int w = threadIdx.x>>5, lane = threadIdx.x&31;
    int row = blockIdx.x*8 + w;
    const float* pr = s0 + (size_t)row*2000;
    float s = 0.f;
    for (int j=lane; j<2000; j+=32) s += pr[j]*Cs[j];
#pragma unroll
    for (int o=16;o;o>>=1) s += __shfl_down_sync(0xffffffffu, s, o);
    if (lane==0) vraw[z*2048 + row] = s;
}
// final scales R=1/v, C=1/u. grid (8,2)
__global__ void scales_k(const float* __restrict__ uraw, const float* __restrict__ vraw,
                         float* __restrict__ Cf, float* __restrict__ Rf){
    int z = blockIdx.y;
    int i = blockIdx.x*256 + threadIdx.x;
    if (i < 2000){
        Cf[z*2048+i] = 1.f/uraw[z*2048+i];
        Rf[z*2048+i] = 1.f/vraw[z*2048+i];
    }
}
// write final s[4000,4000] = blockdiag(s0a*Ra*Ca, s0b*Rb*Cb). grid (16,4000)
__global__ void write_s_k(float* __restrict__ out, const float* __restrict__ s0base,
                          const float* __restrict__ Rf, const float* __restrict__ Cf){
    int row = blockIdx.y;
    int col = blockIdx.x*256 + threadIdx.x;
    if (col >= 4000) return;
    float v = 0.f;
    if (row < 2000 && col < 2000)
        v = s0base[(size_t)row*2000 + col] * Rf[row] * Cf[col];
    else if (row >= 2000 && col >= 2000)
        v = s0base[4000000 + (size_t)(row-2000)*2000 + (col-2000)]
            * Rf[2048 + row-2000] * Cf[2048 + col-2000];
    out[(size_t)row*4000 + col] = v;
}

// ---------------- host-side GEMM dispatch ----------------
static void run_gemm(int ta, int tb, int M, int N, int K,
                     const float* A, int lda, const float* B, int ldb,
                     float* C, int ldc,
                     const float* bias, const float* ks, const float* ms,
                     const float* add, int ldadd, int act, int accum,
                     const float* xsq, const float* ysq, float* gmax)
{
    dim3 grid((N+BN-1)/BN, (M+BM-1)/BM);
    if (!ta && !tb)      gemm_k<false,false><<<grid,256>>>(M,N,K,A,lda,B,ldb,C,ldc,bias,ks,ms,add,ldadd,act,accum,xsq,ysq,gmax);
    else if (!ta && tb)  gemm_k<false,true ><<<grid,256>>>(M,N,K,A,lda,B,ldb,C,ldc,bias,ks,ms,add,ldadd,act,accum,xsq,ysq,gmax);
    else                 gemm_k<true ,false><<<grid,256>>>(M,N,K,A,lda,B,ldb,C,ldc,bias,ks,ms,add,ldadd,act,accum,xsq,ysq,gmax);
}

extern "C" void kernel_launch(void* const* d_in, const int* in_sizes, int n_in,
                              void* d_out, int out_size)
{
    (void)in_sizes; (void)n_in; (void)out_size;
    const float* emb1      = (const float*)d_in[0];
    const float* emb2      = (const float*)d_in[1];
    const float* edge1     = (const float*)d_in[2];
    const float* edge2     = (const float*)d_in[3];
    const float* Asrc      = (const float*)d_in[4];
    const float* Atgt      = (const float*)d_in[5];
    const float* fc1n_w    = (const float*)d_in[6];
    const float* fc1n_b    = (const float*)d_in[7];
    const float* fc2n_w    = (const float*)d_in[8];
    const float* fc2n_b    = (const float*)d_in[9];
    const float* fc1e_w    = (const float*)d_in[10];
    const float* fc1e_b    = (const float*)d_in[11];
    const float* fc2e_w    = (const float*)d_in[12];
    const float* fc2e_b    = (const float*)d_in[13];
    const float* gnn_a_w   = (const float*)d_in[14];
    const float* gnn_a_b   = (const float*)d_in[15];
    const float* gnn_u_w   = (const float*)d_in[16];
    const float* gnn_u_b   = (const float*)d_in[17];
    const float* aff_A     = (const float*)d_in[18];
    const float* cg_w      = (const float*)d_in[19];
    const float* cg_b      = (const float*)d_in[20];

    float* out_s  = (float*)d_out;
    float* out_kp = out_s + 16000000;
    float* out_ke = out_s + 20000000;

    float *h,*xA1,*xB1,*xA2,*xB2,*ax,*ux,*s0,*T1,*Ssym,*cs,*u,*v,*Rf,*Cf,*sq,*gmax;
    cudaGetSymbolAddress((void**)&h,    g_h);
    cudaGetSymbolAddress((void**)&xA1,  g_xA1);
    cudaGetSymbolAddress((void**)&xB1,  g_xB1);
    cudaGetSymbolAddress((void**)&xA2,  g_xA2);
    cudaGetSymbolAddress((void**)&xB2,  g_xB2);
    cudaGetSymbolAddress((void**)&ax,   g_ax);
    cudaGetSymbolAddress((void**)&ux,   g_ux);
    cudaGetSymbolAddress((void**)&s0,   g_s0);
    cudaGetSymbolAddress((void**)&T1,   g_T1);
    cudaGetSymbolAddress((void**)&Ssym, g_Ssym);
    cudaGetSymbolAddress((void**)&cs,   g_cs);
    cudaGetSymbolAddress((void**)&u,    g_u);
    cudaGetSymbolAddress((void**)&v,    g_v);
    cudaGetSymbolAddress((void**)&Rf,   g_Rf);
    cudaGetSymbolAddress((void**)&Cf,   g_Cf);
    cudaGetSymbolAddress((void**)&sq,   g_sq);
    cudaGetSymbolAddress((void**)&gmax, g_gmax);

    const float* Aidx[2] = {Asrc, Atgt};
    float* cur[2] = {xA1, xA2};
    float* alt[2] = {xB1, xB2};

    // ---------- Stage A: node/edge embedding MLPs ----------
    // nodes g1
    run_gemm(0,0, 2000,512,128, emb1,128, fc1n_w,512, h,512, fc1n_b,0,0,0,0,1,0,0,0,0);
    run_gemm(0,0, 2000,256,512, h,512,    fc2n_w,256, cur[0],256, fc2n_b,0,0,0,0,0,0,0,0,0);
    l2norm_k<<<2000,256>>>(cur[0]);
    // nodes g2
    run_gemm(0,0, 2000,512,128, emb2,128, fc1n_w,512, h,512, fc1n_b,0,0,0,0,1,0,0,0,0);
    run_gemm(0,0, 2000,256,512, h,512,    fc2n_w,256, cur[1],256, fc2n_b,0,0,0,0,0,0,0,0,0);
    l2norm_k<<<2000,256>>>(cur[1]);
    // edges g1 (sigmoid)
    run_gemm(0,0, 2000,512,128, edge1,128, fc1e_w,512, h,512, fc1e_b,0,0,0,0,1,0,0,0,0);
    run_gemm(0,0, 2000,256,512, h,512,     fc2e_w,256, cur[0]+2000*256,256, fc2e_b,0,0,0,0,2,0,0,0,0);
    // edges g2
    run_gemm(0,0, 2000,512,128, edge2,128, fc1e_w,512, h,512, fc1e_b,0,0,0,0,1,0,0,0,0);
    run_gemm(0,0, 2000,256,512, h,512,     fc2e_w,256, cur[1]+2000*256,256, fc2e_b,0,0,0,0,2,0,0,0,0);

    // ---------- Kp / Ke pairwise similarity ----------
    rowsq_k<<<2000,256>>>(cur[0],          sq + 0);
    rowsq_k<<<2000,256>>>(cur[1],          sq + 2048);
    rowsq_k<<<2000,256>>>(cur[0]+2000*256, sq + 4096);
    rowsq_k<<<2000,256>>>(cur[1]+2000*256, sq + 6144);
    zero_k<<<1,32>>>(gmax, 2);
    run_gemm(0,1, 2000,2000,256, cur[0],256, cur[1],256, out_kp,2000,
             0,0,0,0,0, 3,0, sq+0,   sq+2048, gmax+0);
    run_gemm(0,1, 2000,2000,256, cur[0]+2000*256,256, cur[1]+2000*256,256, out_ke,2000,
             0,0,0,0,0, 3,0, sq+4096, sq+6144, gmax+1);
    simfin_k<<<(4000000+255)/256,256>>>(out_kp, gmax+0, 4000000);
    simfin_k<<<(4000000+255)/256,256>>>(out_ke, gmax+1, 4000000);

    // ---------- A column L1 sums -> reciprocal scales ----------
    zero_k<<<(8192+255)/256,256>>>(cs, 8192);
    colabs_k<<<dim3(16,32),256>>>(Asrc, cs);
    colabs_k<<<dim3(16,32),256>>>(Atgt, cs+4096);
    recip_clamp_k<<<(8192+255)/256,256>>>(cs, 8192);

    // ---------- GNN layers ----------
    for (int i=0; i<3; ++i){
        const float* wa = gnn_a_w + (size_t)i*65536;
        const float* ba = gnn_a_b + (size_t)i*256;
        const float* wu = gnn_u_w + (size_t)i*65536;
        const float* bu = gnn_u_b + (size_t)i*256;

        for (int g=0; g<2; ++g){
            // ax = relu(x@wa+ba) * (1/colsum)  (fold A's column-L1 normalization)
            run_gemm(0,0, 4000,256,256, cur[g],256, wa,256, ax,256, ba,0, cs+g*4096, 0,0, 1,0,0,0,0);
            // ux = relu(x@wu+bu)
            run_gemm(0,0, 4000,256,256, cur[g],256, wu,256, ux,256, bu,0,0, 0,0, 1,0,0,0,0);
            // y = A @ ax + ux ; then L2 normalize rows
            run_gemm(0,0, 4000,256,4000, Aidx[g],4000, ax,256, alt[g],256, 0,0,0, ux,256, 0,0,0,0,0);
            l2norm_k<<<4000,256>>>(alt[g]);
            float* t_ = cur[g]; cur[g] = alt[g]; alt[g] = t_;
        }

        if (i >= 1){
            // affinity blocks (layer-0 s is dead code)
            ssym_k<<<256,256>>>(aff_A + (size_t)i*65536, Ssym);
            for (int z=0; z<2; ++z){
                size_t off = (size_t)z*2000*256;
                run_gemm(0,0, 2000,256,256, cur[0]+off,256, Ssym,256, T1,256, 0,0,0,0,0,0,0,0,0,0);
                run_gemm(0,1, 2000,2000,256, T1,256, cur[1]+off,256, s0 + (size_t)z*4000000,2000,
                         0,0,0,0,0,0,0,0,0,0);
            }
            softmax_k<<<dim3(2000,2),256>>>(s0);
            // sinkhorn via diagonal scaling (10 alternating mat-vec passes)
            for (int t=0; t<10; ++t){
                if ((t & 1) == 0){
                    zero_k<<<(4096+255)/256,256>>>(u, 4096);
                    sink_col_k<<<dim3(8,16,2),256>>>(s0, v, u, (t==0)?1:0);
                } else {
                    sink_row_k<<<dim3(250,2),256>>>(s0, u, v);
                }
            }
            scales_k<<<dim3(8,2),256>>>(u, v, Cf, Rf);

            if (i == 1){
                // cross-graph: t1 = R.*(s0@(C.*x2)), t2 = C.*(s0^T@(R.*x1)); never materialize s
                for (int z=0; z<2; ++z){
                    size_t off = (size_t)z*2000*256;
                    run_gemm(0,0, 2000,256,2000, s0+(size_t)z*4000000,2000, cur[1]+off,256,
                             ax+off,256, 0, Cf+z*2048, Rf+z*2048, 0,0, 0,0,0,0,0);
                    run_gemm(1,0, 2000,256,2000, s0+(size_t)z*4000000,2000, cur[0]+off,256,
                             ux+off,256, 0, Rf+z*2048, Cf+z*2048, 0,0, 0,0,0,0,0);
                }
                // xn = [x, t] @ cg_w + b   (split as top/bottom 256 rows of cg_w)
                run_gemm(0,0, 4000,256,256, cur[0],256, cg_w,256,        alt[0],256, cg_b,0,0,0,0,0,0,0,0,0);
                run_gemm(0,0, 4000,256,256, ax,256,     cg_w+65536,256,  alt[0],256, 0,0,0,0,0,0,1,0,0,0);
                run_gemm(0,0, 4000,256,256, cur[1],256, cg_w,256,        alt[1],256, cg_b,0,0,0,0,0,0,0,0,0);
                run_gemm(0,0, 4000,256,256, ux,256,     cg_w+65536,256,  alt[1],256, 0,0,0,0,0,0,1,0,0,0);
                float* t0 = cur[0]; cur[0] = alt[0]; alt[0] = t0;
                float* t1 = cur[1]; cur[1] = alt[1]; alt[1] = t1;
            }
            if (i == 2){
                write_s_k<<<dim3(16,4000),256>>>(out_s, s0, Rf, Cf);
            }
        }
    }
}

// round 2
// speedup vs baseline: 1.9425x; 1.9425x over previous
#include <cuda_runtime.h>
#include <math.h>

// ---------------- static scratch (allocation-free rule) ----------------
__device__ float g_h   [2000*512];
__device__ float g_xA1 [4000*256];
__device__ float g_xB1 [4000*256];
__device__ float g_xA2 [4000*256];
__device__ float g_xB2 [4000*256];
__device__ float g_axu [4000*512];
__device__ float g_tc1 [4000*256];
__device__ float g_tc2 [4000*256];
__device__ float g_s0  [2u*2000*2000];
__device__ float g_T1  [2000*256];
__device__ float g_Ssym[256*256];
__device__ float g_wcat[256*512];
__device__ float g_bcat[512];
__device__ float g_cs  [2*4096];
__device__ float g_u   [2*2048];
__device__ float g_v   [2*2048];
__device__ float g_Rf  [2*2048];
__device__ float g_Cf  [2*2048];
__device__ float g_sq  [4*2048];
__device__ float g_gmax[2];
__device__ float g_part[5u*4000*256];   // split-K partials (max 20.5 MB)

// ---------------- reductions ----------------
__device__ __forceinline__ float warpReduceSum(float v){
#pragma unroll
    for (int o=16;o;o>>=1) v += __shfl_xor_sync(0xffffffffu, v, o);
    return v;
}
__device__ __forceinline__ float warpReduceMax(float v){
#pragma unroll
    for (int o=16;o;o>>=1) v = fmaxf(v, __shfl_xor_sync(0xffffffffu, v, o));
    return v;
}
__device__ __forceinline__ float blockReduceSum256(float v){
    __shared__ float sm[8];
    float w = warpReduceSum(v);
    int wi = threadIdx.x>>5, ln = threadIdx.x&31;
    if (ln==0) sm[wi] = w;
    __syncthreads();
    if (wi==0){ float t = (ln<8)?sm[ln]:0.f; t = warpReduceSum(t); if (ln==0) sm[0]=t; }
    __syncthreads();
    float r = sm[0];
    __syncthreads();
    return r;
}
__device__ __forceinline__ float blockReduceMax256(float v){
    __shared__ float sm[8];
    float w = warpReduceMax(v);
    int wi = threadIdx.x>>5, ln = threadIdx.x&31;
    if (ln==0) sm[wi] = w;
    __syncthreads();
    if (wi==0){ float t = (ln<8)?sm[ln]:-1e30f; t = warpReduceMax(t); if (ln==0) sm[0]=t; }
    __syncthreads();
    float r = sm[0];
    __syncthreads();
    return r;
}

// ---------------- generic fp32 GEMM (with optional split-K over gridDim.z) ----
// If gridDim.z > 1: each z computes K-chunk [z*chunk, z*chunk+chunk) and stores a RAW
// partial at C + z*pstride (no epilogue). Otherwise full epilogue:
// C = act( A @ (kscale.*B) + bias + addend (+C if accum) ) .* mscale
// act: 0 none, 1 relu, 2 sigmoid, 3 dist (sqrt(max(xsq+ysq-2v,0)) + global max).
#define BM 128
#define BN 64
#define BK 16

template<bool TA, bool TB>
__global__ __launch_bounds__(256) void gemm_k(
    int M, int N, int K, int chunk, size_t pstride,
    const float* __restrict__ A, int lda,
    const float* __restrict__ B, int ldb,
    float* __restrict__ C, int ldc,
    const float* __restrict__ bias,
    const float* __restrict__ kscale,
    const float* __restrict__ mscale,
    const float* __restrict__ addend, int ldadd,
    int act, int accum,
    const float* __restrict__ xsq, const float* __restrict__ ysq,
    float* __restrict__ gmax)
{
    __shared__ float As[BK][BM+4];
    __shared__ float Bs[BK][BN+4];
    int tid = threadIdx.x;
    int m0 = blockIdx.y * BM;
    int n0 = blockIdx.x * BN;
    int tx = tid & 15, ty = tid >> 4;
    int ml = ty*8, nl = tx*4;

    int kbeg = blockIdx.z * chunk;
    int kend = kbeg + chunk; if (kend > K) kend = K;

    float acc[8][4];
#pragma unroll
    for (int i=0;i<8;++i)
#pragma unroll
        for (int j=0;j<4;++j) acc[i][j] = 0.f;

    for (int k0 = kbeg; k0 < kend; k0 += BK){
        // ---- load A tile ----
        if (!TA){
#pragma unroll
            for (int it=0; it<2; ++it){
                int idx = it*256 + tid;
                int row = idx >> 2;
                int kc  = (idx & 3) << 2;
                float4 vv = make_float4(0.f,0.f,0.f,0.f);
                int gm = m0 + row;
                if (gm < M) vv = *(const float4*)(A + (size_t)gm*lda + k0 + kc);
                As[kc+0][row]=vv.x; As[kc+1][row]=vv.y; As[kc+2][row]=vv.z; As[kc+3][row]=vv.w;
            }
        } else {
#pragma unroll
            for (int it=0; it<2; ++it){
                int idx = it*256 + tid;
                int kk = idx >> 5;
                int mc = (idx & 31) << 2;
                float4 vv = make_float4(0.f,0.f,0.f,0.f);
                int gm = m0 + mc;
                if (gm < M) vv = *(const float4*)(A + (size_t)(k0+kk)*lda + gm);
                *(float4*)(&As[kk][mc]) = vv;
            }
        }
        // ---- load B tile ----
        if (!TB){
            int kk = tid >> 4;
            int nc = (tid & 15) << 2;
            float4 vv = make_float4(0.f,0.f,0.f,0.f);
            int gn = n0 + nc;
            if (gn < N) vv = *(const float4*)(B + (size_t)(k0+kk)*ldb + gn);
            if (kscale){ float s = kscale[k0+kk]; vv.x*=s; vv.y*=s; vv.z*=s; vv.w*=s; }
            *(float4*)(&Bs[kk][nc]) = vv;
        } else {
            int nr = tid >> 2;
            int kc = (tid & 3) << 2;
            float4 vv = make_float4(0.f,0.f,0.f,0.f);
            int gn = n0 + nr;
            if (gn < N) vv = *(const float4*)(B + (size_t)gn*ldb + k0 + kc);
            if (kscale){
                vv.x *= kscale[k0+kc+0]; vv.y *= kscale[k0+kc+1];
                vv.z *= kscale[k0+kc+2]; vv.w *= kscale[k0+kc+3];
            }
            Bs[kc+0][nr]=vv.x; Bs[kc+1][nr]=vv.y; Bs[kc+2][nr]=vv.z; Bs[kc+3][nr]=vv.w;
        }
        __syncthreads();
        // ---- compute ----
#pragma unroll
        for (int kk=0; kk<BK; ++kk){
            float4 a0 = *(const float4*)(&As[kk][ml]);
            float4 a1 = *(const float4*)(&As[kk][ml+4]);
            float4 b0 = *(const float4*)(&Bs[kk][nl]);
            float av[8] = {a0.x,a0.y,a0.z,a0.w,a1.x,a1.y,a1.z,a1.w};
            float bv[4] = {b0.x,b0.y,b0.z,b0.w};
#pragma unroll
            for (int i=0;i<8;++i)
#pragma unroll
                for (int j=0;j<4;++j) acc[i][j] = fmaf(av[i], bv[j], acc[i][j]);
        }
        __syncthreads();
    }

    if (gridDim.z > 1){
        // raw partial store
        float* Cp = C + (size_t)blockIdx.z * pstride;
#pragma unroll
        for (int i=0;i<8;++i){
            int gm = m0 + ml + i;
            if (gm < M){
#pragma unroll
                for (int j=0;j<4;++j){
                    int gn = n0 + nl + j;
                    if (gn < N) Cp[(size_t)gm*ldc + gn] = acc[i][j];
                }
            }
        }
        return;
    }

    // ---- epilogue ----
    float dmax = 0.f;
#pragma unroll
    for (int i=0;i<8;++i){
        int gm = m0 + ml + i;
        if (gm < M){
#pragma unroll
            for (int j=0;j<4;++j){
                int gn = n0 + nl + j;
                if (gn < N){
                    float v = acc[i][j];
                    size_t cidx = (size_t)gm*ldc + gn;
                    if (accum)  v += C[cidx];
                    if (addend) v += addend[(size_t)gm*ldadd + gn];
                    if (bias)   v += bias[gn];
                    if (act==1)      v = fmaxf(v, 0.f);
                    else if (act==2) v = 1.f/(1.f+expf(-v));
                    else if (act==3){
                        v = sqrtf(fmaxf(xsq[gm]+ysq[gn]-2.f*v, 0.f));
                        dmax = fmaxf(dmax, v);
                    }
                    if (mscale) v *= mscale[gm];
                    C[cidx] = v;
                }
            }
        }
    }
    if (act==3){
        __shared__ float red[256];
        red[tid] = dmax; __syncthreads();
        for (int s=128;s;s>>=1){ if (tid<s) red[tid]=fmaxf(red[tid],red[tid+s]); __syncthreads(); }
        if (tid==0) atomicMax((int*)gmax, __float_as_int(red[0]));
    }
}

// ---------------- split-K reducer: one block per row, 256 cols ----------------
// out[row,0:256] = post( sum_z part[z][row] + addend + bias ) ; modes:
// 0: none, 1: row L2 normalize (sqout:=1), 2: sigmoid (+row sumsq -> sqout)
// rowscale (if set) applied last.
__global__ void reduce_k(const float* __restrict__ part, size_t pstride, int SK,
                         const float* __restrict__ addend, int ldadd,
                         const float* __restrict__ bias,
                         const float* __restrict__ rowscale,
                         float* __restrict__ out,
                         float* __restrict__ sqout, int mode)
{
    int row = blockIdx.x, t = threadIdx.x;
    float v = 0.f;
    for (int z=0; z<SK; ++z) v += part[(size_t)z*pstride + (size_t)row*256 + t];
    if (addend) v += addend[(size_t)row*ldadd + t];
    if (bias)   v += bias[t];
    if (mode==1){
        float s = blockReduceSum256(v*v);
        v /= fmaxf(sqrtf(s), 1e-12f);
        if (sqout && t==0) sqout[row] = 1.f;
    } else if (mode==2){
        v = 1.f/(1.f+expf(-v));
        float s = blockReduceSum256(v*v);
        if (sqout && t==0) sqout[row] = s;
    }
    if (rowscale) v *= rowscale[row];
    out[(size_t)row*256 + t] = v;
}

// ---------------- elementwise / misc kernels ----------------
__global__ void zero_k(float* p, int n){
    int i = blockIdx.x*blockDim.x + threadIdx.x;
    if (i < n) p[i] = 0.f;
}
__global__ void recip_clamp_k(float* p, int n){
    int i = blockIdx.x*blockDim.x + threadIdx.x;
    if (i < n) p[i] = 1.f / fmaxf(p[i], 1e-12f);
}
__global__ void simfin_k(float* __restrict__ p, const float* __restrict__ gmax, int n){
    int i = blockIdx.x*blockDim.x + threadIdx.x;
    if (i < n){
        float inv = 1.f / gmax[0];
        p[i] = 1.f - p[i]*inv;
    }
}
// column abs-sum of A[4000,4000]; grid (16,32), block 256
__global__ void colabs_k(const float* __restrict__ A, float* __restrict__ acc){
    int j  = blockIdx.x*256 + threadIdx.x;
    int r0 = blockIdx.y*125;
    if (j >= 4000) return;
    float s = 0.f;
    for (int i=0;i<125;++i) s += fabsf(A[(size_t)(r0+i)*4000 + j]);
    atomicAdd(&acc[j], s);
}
__global__ void ssym_k(const float* __restrict__ A, float* __restrict__ S){
    int i = blockIdx.x, j = threadIdx.x;
    S[i*256+j] = 0.5f*(A[i*256+j] + A[j*256+i]);
}
// pack [wa|wu] -> wcat[256,512], [ba|bu] -> bcat[512]; grid 256, block 512
__global__ void pack_k(const float* __restrict__ wa, const float* __restrict__ wu,
                       const float* __restrict__ ba, const float* __restrict__ bu,
                       float* __restrict__ wcat, float* __restrict__ bcat){
    int r = blockIdx.x, n = threadIdx.x;
    wcat[r*512 + n] = (n < 256) ? wa[r*256 + n] : wu[r*256 + (n-256)];
    if (r == 0) bcat[n] = (n < 256) ? ba[n] : bu[n-256];
}
// softmax(alpha*aff)+eps on 2000-wide rows; off-block adds 2000*exp(-Mx) to denom.
__global__ void softmax_k(float* __restrict__ s0base){
    int z = blockIdx.y, row = blockIdx.x, tid = threadIdx.x;
    float* p = s0base + (size_t)z*4000000 + (size_t)row*2000;
    float a[8]; float mx = -1e30f;
#pragma unroll
    for (int i=0;i<8;++i){
        int c = tid + i*256;
        if (c < 2000){ a[i] = 200.f*p[c]; mx = fmaxf(mx, a[i]); }
        else a[i] = -1e30f;
    }
    float rowmax = blockReduceMax256(mx);
    float Mx = fmaxf(rowmax, 0.f);
    float lsum = 0.f;
#pragma unroll
    for (int i=0;i<8;++i){
        int c = tid + i*256;
        if (c < 2000){ a[i] = expf(a[i]-Mx); lsum += a[i]; }
    }
    float tot = blockReduceSum256(lsum) + 2000.f*expf(-Mx);
    float inv = 1.f/tot;
#pragma unroll
    for (int i=0;i<8;++i){
        int c = tid + i*256;
        if (c < 2000) p[c] = a[i]*inv + 1e-4f;
    }
}
// sinkhorn col pass: u[j] += sum_i s0[i,j]*R[i]. grid (8,16,2)
__global__ void sink_col_k(const float* __restrict__ s0base, const float* __restrict__ vraw,
                           float* __restrict__ uraw, int first){
    int z = blockIdx.z;
    const float* s0 = s0base + (size_t)z*4000000;
    __shared__ float Rs[125];
    int r0 = blockIdx.y*125;
    if (threadIdx.x < 125)
        Rs[threadIdx.x] = first ? 1.f : 1.f/vraw[z*2048 + r0 + threadIdx.x];
    __syncthreads();
    int j = blockIdx.x*256 + threadIdx.x;
    if (j < 2000){
        float s = 0.f;
        for (int i=0;i<125;++i) s += s0[(size_t)(r0+i)*2000 + j]*Rs[i];
        atomicAdd(&uraw[z*2048 + j], s);
    }
}
// sinkhorn row pass: v[i] = sum_j s0[i,j]*(1/uraw[j]). grid (250,2)
__global__ void sink_row_k(const float* __restrict__ s0base, const float* __restrict__ uraw,
                           float* __restrict__ vraw){
    int z = blockIdx.y;
    const float* s0 = s0base + (size_t)z*4000000;
    __shared__ float Cs[2000];
    for (int i=threadIdx.x; i<2000; i+=256) Cs[i] = 1.f/uraw[z*2048 + i];
    __syncthreads();
    int w = threadIdx.x>>5, lane = threadIdx.x&31;
    int row = blockIdx.x*8 + w;
    const float* pr = s0 + (size_t)row*2000;
    float s = 0.f;
    for (int j=lane; j<2000; j+=32) s += pr[j]*Cs[j];
#pragma unroll
    for (int o=16;o;o>>=1) s += __shfl_down_sync(0xffffffffu, s, o);
    if (lane==0) vraw[z*2048 + row] = s;
}
__global__ void scales_k(const float* __restrict__ uraw, const float* __restrict__ vraw,
                         float* __restrict__ Cf, float* __restrict__ Rf){
    int z = blockIdx.y;
    int i = blockIdx.x*256 + threadIdx.x;
    if (i < 2000){
        Cf[z*2048+i] = 1.f/uraw[z*2048+i];
        Rf[z*2048+i] = 1.f/vraw[z*2048+i];
    }
}
__global__ void write_s_k(float* __restrict__ out, const float* __restrict__ s0base,
                          const float* __restrict__ Rf, const float* __restrict__ Cf){
    int row = blockIdx.y;
    int col = blockIdx.x*256 + threadIdx.x;
    if (col >= 4000) return;
    float v = 0.f;
    if (row < 2000 && col < 2000)
        v = s0base[(size_t)row*2000 + col] * Rf[row] * Cf[col];
    else if (row >= 2000 && col >= 2000)
        v = s0base[4000000 + (size_t)(row-2000)*2000 + (col-2000)]
            * Rf[2048 + row-2000] * Cf[2048 + col-2000];
    out[(size_t)row*4000 + col] = v;
}

// ---------------- host-side GEMM dispatch ----------------
static void run_gemm(int ta, int tb, int M, int N, int K,
                     const float* A, int lda, const float* B, int ldb,
                     float* C, int ldc,
                     const float* bias, const float* ks, const float* ms,
                     const float* add, int ldadd, int act, int accum,
                     const float* xsq, const float* ysq, float* gmax)
{
    dim3 grid((N+BN-1)/BN, (M+BM-1)/BM, 1);
    if (!ta && !tb)      gemm_k<false,false><<<grid,256>>>(M,N,K,K,0,A,lda,B,ldb,C,ldc,bias,ks,ms,add,ldadd,act,accum,xsq,ysq,gmax);
    else if (!ta && tb)  gemm_k<false,true ><<<grid,256>>>(M,N,K,K,0,A,lda,B,ldb,C,ldc,bias,ks,ms,add,ldadd,act,accum,xsq,ysq,gmax);
    else                 gemm_k<true ,false><<<grid,256>>>(M,N,K,K,0,A,lda,B,ldb,C,ldc,bias,ks,ms,add,ldadd,act,accum,xsq,ysq,gmax);
}
// split-K: raw partials into part (pstride = M*N), epilogue in reduce_k
static void run_gemm_split(int ta, int M, int N, int K,
                           const float* A, int lda, const float* B, int ldb,
                           float* part, const float* ks, int SK, int chunk)
{
    dim3 grid((N+BN-1)/BN, (M+BM-1)/BM, SK);
    size_t ps = (size_t)M*N;
    if (!ta) gemm_k<false,false><<<grid,256>>>(M,N,K,chunk,ps,A,lda,B,ldb,part,N,0,ks,0,0,0,0,0,0,0,0);
    else     gemm_k<true ,false><<<grid,256>>>(M,N,K,chunk,ps,A,lda,B,ldb,part,N,0,ks,0,0,0,0,0,0,0,0);
}

extern "C" void kernel_launch(void* const* d_in, const int* in_sizes, int n_in,
                              void* d_out, int out_size)
{
    (void)in_sizes; (void)n_in; (void)out_size;
    const float* emb1      = (const float*)d_in[0];
    const float* emb2      = (const float*)d_in[1];
    const float* edge1     = (const float*)d_in[2];
    const float* edge2     = (const float*)d_in[3];
    const float* Asrc      = (const float*)d_in[4];
    const float* Atgt      = (const float*)d_in[5];
    const float* fc1n_w    = (const float*)d_in[6];
    const float* fc1n_b    = (const float*)d_in[7];
    const float* fc2n_w    = (const float*)d_in[8];
    const float* fc2n_b    = (const float*)d_in[9];
    const float* fc1e_w    = (const float*)d_in[10];
    const float* fc1e_b    = (const float*)d_in[11];
    const float* fc2e_w    = (const float*)d_in[12];
    const float* fc2e_b    = (const float*)d_in[13];
    const float* gnn_a_w   = (const float*)d_in[14];
    const float* gnn_a_b   = (const float*)d_in[15];
    const float* gnn_u_w   = (const float*)d_in[16];
    const float* gnn_u_b   = (const float*)d_in[17];
    const float* aff_A     = (const float*)d_in[18];
    const float* cg_w      = (const float*)d_in[19];
    const float* cg_b      = (const float*)d_in[20];

    float* out_s  = (float*)d_out;
    float* out_kp = out_s + 16000000;
    float* out_ke = out_s + 20000000;

    float *h,*xA1,*xB1,*xA2,*xB2,*axu,*tc1,*tc2,*s0,*T1,*Ssym,*wcat,*bcat;
    float *cs,*u,*v,*Rf,*Cf,*sq,*gmax,*part;
    cudaGetSymbolAddress((void**)&h,    g_h);
    cudaGetSymbolAddress((void**)&xA1,  g_xA1);
    cudaGetSymbolAddress((void**)&xB1,  g_xB1);
    cudaGetSymbolAddress((void**)&xA2,  g_xA2);
    cudaGetSymbolAddress((void**)&xB2,  g_xB2);
    cudaGetSymbolAddress((void**)&axu,  g_axu);
    cudaGetSymbolAddress((void**)&tc1,  g_tc1);
    cudaGetSymbolAddress((void**)&tc2,  g_tc2);
    cudaGetSymbolAddress((void**)&s0,   g_s0);
    cudaGetSymbolAddress((void**)&T1,   g_T1);
    cudaGetSymbolAddress((void**)&Ssym, g_Ssym);
    cudaGetSymbolAddress((void**)&wcat, g_wcat);
    cudaGetSymbolAddress((void**)&bcat, g_bcat);
    cudaGetSymbolAddress((void**)&cs,   g_cs);
    cudaGetSymbolAddress((void**)&u,    g_u);
    cudaGetSymbolAddress((void**)&v,    g_v);
    cudaGetSymbolAddress((void**)&Rf,   g_Rf);
    cudaGetSymbolAddress((void**)&Cf,   g_Cf);
    cudaGetSymbolAddress((void**)&sq,   g_sq);
    cudaGetSymbolAddress((void**)&gmax, g_gmax);
    cudaGetSymbolAddress((void**)&part, g_part);

    const float* Aidx[2] = {Asrc, Atgt};
    float* cur[2] = {xA1, xA2};
    float* alt[2] = {xB1, xB2};

    // ---------- Stage A: node/edge embedding MLPs (fc2 split-K, fused epilogues) ----------
    // nodes g1
    run_gemm(0,0, 2000,512,128, emb1,128, fc1n_w,512, h,512, fc1n_b,0,0,0,0,1,0,0,0,0);
    run_gemm_split(0, 2000,256,512, h,512, fc2n_w,256, part, 0, 4, 128);
    reduce_k<<<2000,256>>>(part, 2000*256, 4, 0,0, fc2n_b, 0, cur[0], sq+0, 1);
    // nodes g2
    run_gemm(0,0, 2000,512,128, emb2,128, fc1n_w,512, h,512, fc1n_b,0,0,0,0,1,0,0,0,0);
    run_gemm_split(0, 2000,256,512, h,512, fc2n_w,256, part, 0, 4, 128);
    reduce_k<<<2000,256>>>(part, 2000*256, 4, 0,0, fc2n_b, 0, cur[1], sq+2048, 1);
    // edges g1 (sigmoid)
    run_gemm(0,0, 2000,512,128, edge1,128, fc1e_w,512, h,512, fc1e_b,0,0,0,0,1,0,0,0,0);
    run_gemm_split(0, 2000,256,512, h,512, fc2e_w,256, part, 0, 4, 128);
    reduce_k<<<2000,256>>>(part, 2000*256, 4, 0,0, fc2e_b, 0, cur[0]+2000*256, sq+4096, 2);
    // edges g2
    run_gemm(0,0, 2000,512,128, edge2,128, fc1e_w,512, h,512, fc1e_b,0,0,0,0,1,0,0,0,0);
    run_gemm_split(0, 2000,256,512, h,512, fc2e_w,256, part, 0, 4, 128);
    reduce_k<<<2000,256>>>(part, 2000*256, 4, 0,0, fc2e_b, 0, cur[1]+2000*256, sq+6144, 2);

    // ---------- Kp / Ke pairwise similarity ----------
    zero_k<<<1,32>>>(gmax, 2);
    run_gemm(0,1, 2000,2000,256, cur[0],256, cur[1],256, out_kp,2000,
             0,0,0,0,0, 3,0, sq+0,   sq+2048, gmax+0);
    run_gemm(0,1, 2000,2000,256, cur[0]+2000*256,256, cur[1]+2000*256,256, out_ke,2000,
             0,0,0,0,0, 3,0, sq+4096, sq+6144, gmax+1);
    simfin_k<<<(4000000+255)/256,256>>>(out_kp, gmax+0, 4000000);
    simfin_k<<<(4000000+255)/256,256>>>(out_ke, gmax+1, 4000000);

    // ---------- A column L1 sums -> reciprocal scales ----------
    zero_k<<<(8192+255)/256,256>>>(cs, 8192);
    colabs_k<<<dim3(16,32),256>>>(Asrc, cs);
    colabs_k<<<dim3(16,32),256>>>(Atgt, cs+4096);
    recip_clamp_k<<<(8192+255)/256,256>>>(cs, 8192);

    // ---------- GNN layers ----------
    for (int i=0; i<3; ++i){
        pack_k<<<256,512>>>(gnn_a_w + (size_t)i*65536, gnn_u_w + (size_t)i*65536,
                            gnn_a_b + (size_t)i*256,   gnn_u_b + (size_t)i*256,
                            wcat, bcat);

        for (int g=0; g<2; ++g){
            // axu = relu(x @ [wa|wu] + [ba|bu])  (ax = cols 0-255, ux = cols 256-511)
            run_gemm(0,0, 4000,512,256, cur[g],256, wcat,512, axu,512, bcat,0,0,0,0,1,0,0,0,0);
            // y = A @ (cs .* ax) + ux ; l2norm rows  (colsum scale folded as k-scale)
            run_gemm_split(0, 4000,256,4000, Aidx[g],4000, axu,512, part, cs+g*4096, 5, 800);
            reduce_k<<<4000,256>>>(part, 4000*256, 5, axu+256,512, 0, 0, alt[g], 0, 1);
            float* t_ = cur[g]; cur[g] = alt[g]; alt[g] = t_;
        }

        if (i >= 1){
            // affinity blocks (layer-0 s is dead code)
            ssym_k<<<256,256>>>(aff_A + (size_t)i*65536, Ssym);
            for (int z=0; z<2; ++z){
                size_t off = (size_t)z*2000*256;
                run_gemm_split(0, 2000,256,256, cur[0]+off,256, Ssym,256, part, 0, 2, 128);
                reduce_k<<<2000,256>>>(part, 2000*256, 2, 0,0, 0, 0, T1, 0, 0);
                run_gemm(0,1, 2000,2000,256, T1,256, cur[1]+off,256, s0 + (size_t)z*4000000,2000,
                         0,0,0,0,0,0,0,0,0,0);
            }
            softmax_k<<<dim3(2000,2),256>>>(s0);
            // sinkhorn via diagonal scaling
            for (int t=0; t<10; ++t){
                if ((t & 1) == 0){
                    zero_k<<<(4096+255)/256,256>>>(u, 4096);
                    sink_col_k<<<dim3(8,16,2),256>>>(s0, v, u, (t==0)?1:0);
                } else {
                    sink_row_k<<<dim3(250,2),256>>>(s0, u, v);
                }
            }
            scales_k<<<dim3(8,2),256>>>(u, v, Cf, Rf);

            if (i == 1){
                // cross-graph: t1 = R.*(s0@(C.*x2)), t2 = C.*(s0^T@(R.*x1))
                for (int z=0; z<2; ++z){
                    size_t off = (size_t)z*2000*256;
                    run_gemm_split(0, 2000,256,2000, s0+(size_t)z*4000000,2000, cur[1]+off,256,
                                   part, Cf+z*2048, 5, 400);
                    reduce_k<<<2000,256>>>(part, 2000*256, 5, 0,0, 0, Rf+z*2048, tc1+off, 0, 0);
                    run_gemm_split(1, 2000,256,2000, s0+(size_t)z*4000000,2000, cur[0]+off,256,
                                   part, Rf+z*2048, 5, 400);
                    reduce_k<<<2000,256>>>(part, 2000*256, 5, 0,0, 0, Cf+z*2048, tc2+off, 0, 0);
                }
                // xn = [x, t] @ cg_w + b   (top/bottom halves of cg_w)
                run_gemm(0,0, 4000,256,256, cur[0],256, cg_w,256,        alt[0],256, cg_b,0,0,0,0,0,0,0,0,0);
                run_gemm(0,0, 4000,256,256, tc1,256,    cg_w+65536,256,  alt[0],256, 0,0,0,0,0,0,1,0,0,0);
                run_gemm(0,0, 4000,256,256, cur[1],256, cg_w,256,        alt[1],256, cg_b,0,0,0,0,0,0,0,0,0);
                run_gemm(0,0, 4000,256,256, tc2,256,    cg_w+65536,256,  alt[1],256, 0,0,0,0,0,0,1,0,0,0);
                float* t0 = cur[0]; cur[0] = alt[0]; alt[0] = t0;
                float* t1 = cur[1]; cur[1] = alt[1]; alt[1] = t1;
            }
            if (i == 2){
                write_s_k<<<dim3(16,4000),256>>>(out_s, s0, Rf, Cf);
            }
        }
    }
}